// round 2
// baseline (speedup 1.0000x reference)
#include <cuda_runtime.h>

// Soft decision tree ensemble:
//   N_TREES=15, DEPTH=3 (7 internal, 8 leaves), INPUT_DIM=128, N_CLASSES=10, batch=262144
//
// Strategy:
//   prep_kernel: softmax tree weights + per-(tree,leaf) class softmax, pre-scaled
//                by tree weight -> g_lcp (tiny).
//   main_kernel: 128 threads/block, 256 rows/block. Stage x tile (256x128, padded
//                stride 132 for conflict-free LDS.128) + all split weights (53.8KB)
//                in dynamic smem. Each thread handles 2 rows; z accumulated with
//                packed fma.rn.f32x2 (2 FMAs/instr) over d-pairs. Epilogue
//                (sigmoid -> leaf path products -> class mix) also f32x2-packed.

#define NTREES 15
#define NI 7
#define NL 8
#define NC 10
#define DIM 128
#define PER_TREE (NI*DIM + NI + NL*NC)   // 983
#define ROWS_PER_BLOCK 256
#define THREADS 128
#define XS_STRIDE 132                    // pad: conflict-free LDS.128 within 8-lane phases

#define WS_FLOATS (NTREES*NI*DIM)        // 13440
#define BS_OFF    WS_FLOATS              // biases, padded to 112
#define LCP_OFF   (BS_OFF + 112)         // 1200 scaled leaf-class probs
#define XS_OFF    (LCP_OFF + NTREES*NL*NC)
#define SMEM_FLOATS (XS_OFF + ROWS_PER_BLOCK*XS_STRIDE)
#define SMEM_BYTES  (SMEM_FLOATS * 4)    // 194176 bytes

typedef unsigned long long u64;

__device__ float g_lcp[NTREES*NL*NC];

__device__ __forceinline__ void fma2(u64 &d, u64 a, u64 b) {
    asm("fma.rn.f32x2 %0, %1, %2, %0;" : "+l"(d) : "l"(a), "l"(b));
}
__device__ __forceinline__ u64 splat2(float f) {
    u64 r; asm("mov.b64 %0, {%1, %1};" : "=l"(r) : "f"(f)); return r;
}
__device__ __forceinline__ float2 unpack2(u64 v) {
    float2 f; asm("mov.b64 {%0, %1}, %2;" : "=f"(f.x), "=f"(f.y) : "l"(v)); return f;
}
__device__ __forceinline__ float fast_sigmoid(float z) {
    return __fdividef(1.0f, 1.0f + __expf(-z));
}

// ---------------------------------------------------------------------------
// Prep: tree-weight softmax + leaf-logit softmax, pre-scaled into g_lcp.
// ---------------------------------------------------------------------------
__global__ void prep_kernel(const float* __restrict__ params) {
    __shared__ float tw[NTREES];
    int tid = threadIdx.x;
    if (tid == 0) {
        const float* twl = params + NTREES * PER_TREE;
        float m = -1e30f;
        for (int t = 0; t < NTREES; t++) m = fmaxf(m, twl[t]);
        float e[NTREES]; float s = 0.f;
        for (int t = 0; t < NTREES; t++) { e[t] = __expf(twl[t] - m); s += e[t]; }
        float inv = __fdividef(1.0f, s);
        for (int t = 0; t < NTREES; t++) tw[t] = e[t] * inv;
    }
    __syncthreads();
    for (int i = tid; i < NTREES * NL; i += blockDim.x) {
        int t = i / NL, l = i % NL;
        const float* lg = params + t * PER_TREE + NI * DIM + NI + l * NC;
        float m = -1e30f;
        #pragma unroll
        for (int c = 0; c < NC; c++) m = fmaxf(m, lg[c]);
        float e[NC]; float s = 0.f;
        #pragma unroll
        for (int c = 0; c < NC; c++) { e[c] = __expf(lg[c] - m); s += e[c]; }
        float scale = tw[t] * __fdividef(1.0f, s);
        #pragma unroll
        for (int c = 0; c < NC; c++) g_lcp[i * NC + c] = e[c] * scale;
    }
}

// ---------------------------------------------------------------------------
// Main kernel
// ---------------------------------------------------------------------------
__global__ __launch_bounds__(THREADS, 1)
void tree_main_kernel(const float* __restrict__ x,
                      const float* __restrict__ params,
                      float* __restrict__ out) {
    extern __shared__ float smem[];
    float* ws  = smem;
    float* bs  = smem + BS_OFF;
    float* lcp = smem + LCP_OFF;
    float* xs  = smem + XS_OFF;

    int tid = threadIdx.x;

    // Stage weights/biases/leaf-class-probs (once per block; L2-served).
    for (int i = tid; i < WS_FLOATS; i += THREADS) {
        int t = i / (NI * DIM); int r = i - t * (NI * DIM);
        ws[i] = params[t * PER_TREE + r];
    }
    for (int i = tid; i < NTREES * NI; i += THREADS) {
        int t = i / NI; int n = i - t * NI;
        bs[i] = params[t * PER_TREE + NI * DIM + n];
    }
    for (int i = tid; i < NTREES * NL * NC; i += THREADS) lcp[i] = g_lcp[i];

    // Stage x tile: coalesced float4 loads, padded-stride smem stores.
    const float4* xg = (const float4*)(x + (long)blockIdx.x * ROWS_PER_BLOCK * DIM);
    #pragma unroll
    for (int k = 0; k < (ROWS_PER_BLOCK * DIM / 4) / THREADS; k++) {
        int idx = k * THREADS + tid;
        int row = idx >> 5, c4 = idx & 31;     // 32 float4 per row
        ((float4*)(xs + row * XS_STRIDE))[c4] = xg[idx];
    }
    __syncthreads();

    const float* x0 = xs + tid * XS_STRIDE;
    const float* x1 = xs + (tid + 128) * XS_STRIDE;

    u64 out0[5], out1[5];
    #pragma unroll
    for (int c = 0; c < 5; c++) { out0[c] = 0ull; out1[c] = 0ull; }

    for (int t = 0; t < NTREES; t++) {
        const float* wt = ws + t * NI * DIM;
        u64 a0[NI], a1[NI];
        #pragma unroll
        for (int n = 0; n < NI; n++) { a0[n] = 0ull; a1[n] = 0ull; }

        #pragma unroll 4
        for (int d4 = 0; d4 < DIM / 4; d4++) {
            ulonglong2 xa = ((const ulonglong2*)x0)[d4];
            ulonglong2 xb = ((const ulonglong2*)x1)[d4];
            #pragma unroll
            for (int n = 0; n < NI; n++) {
                ulonglong2 wv = ((const ulonglong2*)(wt + n * DIM))[d4];
                fma2(a0[n], xa.x, wv.x);
                fma2(a0[n], xa.y, wv.y);
                fma2(a1[n], xb.x, wv.x);
                fma2(a1[n], xb.y, wv.y);
            }
        }

        // z -> sigmoid (prob of going RIGHT)
        float p0[NI], p1[NI];
        #pragma unroll
        for (int n = 0; n < NI; n++) {
            float2 f0 = unpack2(a0[n]);
            float2 f1 = unpack2(a1[n]);
            float b = bs[t * NI + n];
            p0[n] = fast_sigmoid(f0.x + f0.y + b);
            p1[n] = fast_sigmoid(f1.x + f1.y + b);
        }

        // Leaf path products (node 0 root; children 2i+1=left, 2i+2=right).
        float lp0[NL], lp1[NL];
        {
            float c1 = 1.f - p0[0], c2 = p0[0];
            float c3 = c1 * (1.f - p0[1]), c4v = c1 * p0[1];
            float c5 = c2 * (1.f - p0[2]), c6 = c2 * p0[2];
            lp0[0] = c3 * (1.f - p0[3]);  lp0[1] = c3 * p0[3];
            lp0[2] = c4v * (1.f - p0[4]); lp0[3] = c4v * p0[4];
            lp0[4] = c5 * (1.f - p0[5]);  lp0[5] = c5 * p0[5];
            lp0[6] = c6 * (1.f - p0[6]);  lp0[7] = c6 * p0[6];
        }
        {
            float c1 = 1.f - p1[0], c2 = p1[0];
            float c3 = c1 * (1.f - p1[1]), c4v = c1 * p1[1];
            float c5 = c2 * (1.f - p1[2]), c6 = c2 * p1[2];
            lp1[0] = c3 * (1.f - p1[3]);  lp1[1] = c3 * p1[3];
            lp1[2] = c4v * (1.f - p1[4]); lp1[3] = c4v * p1[4];
            lp1[4] = c5 * (1.f - p1[5]);  lp1[5] = c5 * p1[5];
            lp1[6] = c6 * (1.f - p1[6]);  lp1[7] = c6 * p1[6];
        }

        // Mix into class accumulators (lcp pre-scaled by tree weight).
        const u64* lt = (const u64*)(lcp + t * NL * NC);
        #pragma unroll
        for (int l = 0; l < NL; l++) {
            u64 s0 = splat2(lp0[l]);
            u64 s1 = splat2(lp1[l]);
            #pragma unroll
            for (int c = 0; c < 5; c++) {
                u64 w2 = lt[l * 5 + c];
                fma2(out0[c], s0, w2);
                fma2(out1[c], s1, w2);
            }
        }
    }

    // Write results: 10 floats per row as 5 float2 stores.
    float2* og = (float2*)(out + (long)blockIdx.x * ROWS_PER_BLOCK * NC);
    #pragma unroll
    for (int c = 0; c < 5; c++) {
        og[tid * 5 + c]         = unpack2(out0[c]);
        og[(tid + 128) * 5 + c] = unpack2(out1[c]);
    }
}

// ---------------------------------------------------------------------------
extern "C" void kernel_launch(void* const* d_in, const int* in_sizes, int n_in,
                              void* d_out, int out_size) {
    const float* x      = (const float*)d_in[0];
    const float* params = (const float*)d_in[1];
    float* out          = (float*)d_out;
    int batch = in_sizes[0] / DIM;

    cudaFuncSetAttribute(tree_main_kernel,
                         cudaFuncAttributeMaxDynamicSharedMemorySize, SMEM_BYTES);

    prep_kernel<<<1, 128>>>(params);
    tree_main_kernel<<<batch / ROWS_PER_BLOCK, THREADS, SMEM_BYTES>>>(x, params, out);
}

// round 9
// speedup vs baseline: 1.0669x; 1.0669x over previous
#include <cuda_runtime.h>

// Soft decision tree ensemble:
//   N_TREES=15, DEPTH=3 (7 internal, 8 leaves), INPUT_DIM=128, N_CLASSES=10, batch=262144
//
// R4 = R2 architecture with the xr load-loop bound fixed (DIM/8 -> DIM/4):
//   - 256 threads/block, 1 row per thread, row held ENTIRELY in registers
//     (64 packed f32x2 u64), loaded once via a padded conflict-free smem stage
//     and reused across all 15 trees -> per-tree inner loop is only
//     7 broadcast weight LDS.128 + 14 fma.rn.f32x2 per d4 step.
//   - 8 warps/SM (2 per SMSP) to cover LDS/FFMA latency; FFMA2 pipe is the
//     intended limiter (~1792 cyc/tree/SM).
//   - prep_kernel pre-softmaxes tree weights and leaf-class logits, pre-scaled
//     by tree weight -> class mix is a plain f32x2 FMA.

#define NTREES 15
#define NI 7
#define NL 8
#define NC 10
#define DIM 128
#define PER_TREE (NI*DIM + NI + NL*NC)   // 983
#define ROWS_PER_BLOCK 256
#define THREADS 256
#define XS_STRIDE 132                    // stride%32==4 -> conflict-free LDS.128 per 8-lane phase

#define WS_FLOATS (NTREES*NI*DIM)        // 13440
#define BS_OFF    WS_FLOATS
#define LCP_OFF   (BS_OFF + 112)
#define XS_OFF    (LCP_OFF + NTREES*NL*NC)
#define SMEM_FLOATS (XS_OFF + ROWS_PER_BLOCK*XS_STRIDE)
#define SMEM_BYTES  (SMEM_FLOATS * 4)    // 194176 bytes

typedef unsigned long long u64;

__device__ float g_lcp[NTREES*NL*NC];

__device__ __forceinline__ void fma2(u64 &d, u64 a, u64 b) {
    asm("fma.rn.f32x2 %0, %1, %2, %0;" : "+l"(d) : "l"(a), "l"(b));
}
__device__ __forceinline__ u64 splat2(float f) {
    u64 r; asm("mov.b64 %0, {%1, %1};" : "=l"(r) : "f"(f)); return r;
}
__device__ __forceinline__ float2 unpack2(u64 v) {
    float2 f; asm("mov.b64 {%0, %1}, %2;" : "=f"(f.x), "=f"(f.y) : "l"(v)); return f;
}
__device__ __forceinline__ float fast_sigmoid(float z) {
    return __fdividef(1.0f, 1.0f + __expf(-z));
}

// ---------------------------------------------------------------------------
// Prep: tree-weight softmax + leaf-logit softmax, pre-scaled into g_lcp.
// ---------------------------------------------------------------------------
__global__ void prep_kernel(const float* __restrict__ params) {
    __shared__ float tw[NTREES];
    int tid = threadIdx.x;
    if (tid == 0) {
        const float* twl = params + NTREES * PER_TREE;
        float m = -1e30f;
        for (int t = 0; t < NTREES; t++) m = fmaxf(m, twl[t]);
        float e[NTREES]; float s = 0.f;
        for (int t = 0; t < NTREES; t++) { e[t] = __expf(twl[t] - m); s += e[t]; }
        float inv = __fdividef(1.0f, s);
        for (int t = 0; t < NTREES; t++) tw[t] = e[t] * inv;
    }
    __syncthreads();
    for (int i = tid; i < NTREES * NL; i += blockDim.x) {
        int t = i / NL, l = i % NL;
        const float* lg = params + t * PER_TREE + NI * DIM + NI + l * NC;
        float m = -1e30f;
        #pragma unroll
        for (int c = 0; c < NC; c++) m = fmaxf(m, lg[c]);
        float e[NC]; float s = 0.f;
        #pragma unroll
        for (int c = 0; c < NC; c++) { e[c] = __expf(lg[c] - m); s += e[c]; }
        float scale = tw[t] * __fdividef(1.0f, s);
        #pragma unroll
        for (int c = 0; c < NC; c++) g_lcp[i * NC + c] = e[c] * scale;
    }
}

// ---------------------------------------------------------------------------
// Main kernel: 256 threads, 1 row/thread in registers.
// ---------------------------------------------------------------------------
__global__ __launch_bounds__(THREADS, 1)
void tree_main_kernel(const float* __restrict__ x,
                      const float* __restrict__ params,
                      float* __restrict__ out) {
    extern __shared__ float smem[];
    float* ws  = smem;
    float* bs  = smem + BS_OFF;
    float* lcp = smem + LCP_OFF;
    float* xs  = smem + XS_OFF;

    int tid = threadIdx.x;

    // Stage weights/biases/leaf-class-probs.
    for (int i = tid; i < WS_FLOATS; i += THREADS) {
        int t = i / (NI * DIM); int r = i - t * (NI * DIM);
        ws[i] = params[t * PER_TREE + r];
    }
    if (tid < NTREES * NI) {
        int t = tid / NI; int n = tid - t * NI;
        bs[tid] = params[t * PER_TREE + NI * DIM + n];
    }
    for (int i = tid; i < NTREES * NL * NC; i += THREADS) lcp[i] = g_lcp[i];

    // Stage x tile: coalesced float4 global loads -> padded smem rows.
    const float4* xg = (const float4*)(x + (long)blockIdx.x * ROWS_PER_BLOCK * DIM);
    #pragma unroll
    for (int k = 0; k < (ROWS_PER_BLOCK * DIM / 4) / THREADS; k++) {
        int idx = k * THREADS + tid;
        int row = idx >> 5, c4 = idx & 31;
        ((float4*)(xs + row * XS_STRIDE))[c4] = xg[idx];
    }
    __syncthreads();

    // Pull this thread's FULL row into registers: 32 ulonglong2 loads
    // (16 B each) = 128 floats = 64 packed f32x2.  [R2 bug: bound was DIM/8]
    u64 xr[DIM / 2];
    {
        const ulonglong2* xrow = (const ulonglong2*)(xs + tid * XS_STRIDE);
        #pragma unroll
        for (int j = 0; j < DIM / 4; j++) {
            ulonglong2 v = xrow[j];
            xr[2 * j]     = v.x;
            xr[2 * j + 1] = v.y;
        }
    }

    u64 outacc[5];
    #pragma unroll
    for (int c = 0; c < 5; c++) outacc[c] = 0ull;

    #pragma unroll 1
    for (int t = 0; t < NTREES; t++) {
        const float* wt = ws + t * NI * DIM;
        u64 a[NI];
        #pragma unroll
        for (int n = 0; n < NI; n++) a[n] = 0ull;

        // Inner GEMV: weight loads are warp-uniform (broadcast LDS.128),
        // x comes from registers.
        #pragma unroll
        for (int d4 = 0; d4 < DIM / 4; d4++) {
            #pragma unroll
            for (int n = 0; n < NI; n++) {
                ulonglong2 wv = ((const ulonglong2*)(wt + n * DIM))[d4];
                fma2(a[n], xr[2 * d4],     wv.x);
                fma2(a[n], xr[2 * d4 + 1], wv.y);
            }
        }

        // z -> sigmoid (prob of going RIGHT at each internal node)
        float p[NI];
        #pragma unroll
        for (int n = 0; n < NI; n++) {
            float2 f = unpack2(a[n]);
            p[n] = fast_sigmoid(f.x + f.y + bs[t * NI + n]);
        }

        // Leaf path products (node 0 root; children 2i+1=left, 2i+2=right).
        float lp[NL];
        {
            float c1 = 1.f - p[0], c2 = p[0];
            float c3 = c1 * (1.f - p[1]), c4v = c1 * p[1];
            float c5 = c2 * (1.f - p[2]), c6 = c2 * p[2];
            lp[0] = c3 * (1.f - p[3]);  lp[1] = c3 * p[3];
            lp[2] = c4v * (1.f - p[4]); lp[3] = c4v * p[4];
            lp[4] = c5 * (1.f - p[5]);  lp[5] = c5 * p[5];
            lp[6] = c6 * (1.f - p[6]);  lp[7] = c6 * p[6];
        }

        // Mix into class accumulators (lcp pre-scaled by tree weight).
        const u64* lt = (const u64*)(lcp + t * NL * NC);
        #pragma unroll
        for (int l = 0; l < NL; l++) {
            u64 s = splat2(lp[l]);
            #pragma unroll
            for (int c = 0; c < 5; c++) {
                fma2(outacc[c], s, lt[l * 5 + c]);
            }
        }
    }

    // Write 10 floats for this row as 5 float2 stores.
    float2* og = (float2*)(out + ((long)blockIdx.x * ROWS_PER_BLOCK + tid) * NC);
    #pragma unroll
    for (int c = 0; c < 5; c++) og[c] = unpack2(outacc[c]);
}

// ---------------------------------------------------------------------------
extern "C" void kernel_launch(void* const* d_in, const int* in_sizes, int n_in,
                              void* d_out, int out_size) {
    const float* x      = (const float*)d_in[0];
    const float* params = (const float*)d_in[1];
    float* out          = (float*)d_out;
    int batch = in_sizes[0] / DIM;

    cudaFuncSetAttribute(tree_main_kernel,
                         cudaFuncAttributeMaxDynamicSharedMemorySize, SMEM_BYTES);

    prep_kernel<<<1, 128>>>(params);
    tree_main_kernel<<<batch / ROWS_PER_BLOCK, THREADS, SMEM_BYTES>>>(x, params, out);
}

// round 10
// speedup vs baseline: 1.2201x; 1.1436x over previous
#include <cuda_runtime.h>

// Soft decision tree ensemble:
//   N_TREES=15, DEPTH=3 (7 internal, 8 leaves), INPUT_DIM=128, N_CLASSES=10, batch=262144
//
// R9: d-split across warp halves to halve broadcast weight-LDS traffic
//   (measured binder in R4: L1tex wavefronts at 78.7%, broadcast LDS.128 ~ 2wf).
//   - 256 threads, 256 rows/block. Warps 0-3 compute d[0:64), warps 4-7 d[64:128),
//     each thread holds 2 half-rows of x in registers (128 regs, same as R4).
//   - Partial z exchanged via stride-9 padded smem (conflict-free STS/LDS.32),
//     double-buffered, one __syncthreads per tree.
//   - Each thread owns exactly one row's epilogue (sigmoid/leaf/class-mix).
//   - Leaf-class probs (pre-scaled by tree softmax weight) live in __constant__,
//     filled by a D2D memcpy node after prep_kernel (uniform-constant port,
//     off the LSU pipe).
//   - fma.rn.f32x2 packing throughout.

#define NTREES 15
#define NI 7
#define NL 8
#define NC 10
#define DIM 128
#define HALF 64
#define PER_TREE (NI*DIM + NI + NL*NC)   // 983
#define ROWS_PER_BLOCK 256
#define THREADS 256
#define XS_STRIDE 132                    // %32==4 -> conflict-free LDS.128 per 8-lane phase

#define WS_FLOATS (NTREES*NI*DIM)        // 13440
#define BS_OFF    WS_FLOATS              // 112 (padded)
#define ZB_OFF    (BS_OFF + 112)         // 2 * 256*9 = 4608
#define ZB_STRIDE (ROWS_PER_BLOCK*9)     // 2304
#define XS_OFF    (ZB_OFF + 2*ZB_STRIDE)
#define SMEM_FLOATS (XS_OFF + ROWS_PER_BLOCK*XS_STRIDE)   // 51952
#define SMEM_BYTES  (SMEM_FLOATS * 4)    // 207808 bytes

typedef unsigned long long u64;

__device__ float g_lcp[NTREES*NL*NC];
__constant__ float c_lcp[NTREES*NL*NC];

__device__ __forceinline__ void fma2(u64 &d, u64 a, u64 b) {
    asm("fma.rn.f32x2 %0, %1, %2, %0;" : "+l"(d) : "l"(a), "l"(b));
}
__device__ __forceinline__ u64 splat2(float f) {
    u64 r; asm("mov.b64 %0, {%1, %1};" : "=l"(r) : "f"(f)); return r;
}
__device__ __forceinline__ float2 unpack2(u64 v) {
    float2 f; asm("mov.b64 {%0, %1}, %2;" : "=f"(f.x), "=f"(f.y) : "l"(v)); return f;
}
__device__ __forceinline__ float fast_sigmoid(float z) {
    return __fdividef(1.0f, 1.0f + __expf(-z));
}

// ---------------------------------------------------------------------------
// Prep: tree-weight softmax + leaf-logit softmax, pre-scaled into g_lcp.
// ---------------------------------------------------------------------------
__global__ void prep_kernel(const float* __restrict__ params) {
    __shared__ float tw[NTREES];
    int tid = threadIdx.x;
    if (tid == 0) {
        const float* twl = params + NTREES * PER_TREE;
        float m = -1e30f;
        for (int t = 0; t < NTREES; t++) m = fmaxf(m, twl[t]);
        float e[NTREES]; float s = 0.f;
        for (int t = 0; t < NTREES; t++) { e[t] = __expf(twl[t] - m); s += e[t]; }
        float inv = __fdividef(1.0f, s);
        for (int t = 0; t < NTREES; t++) tw[t] = e[t] * inv;
    }
    __syncthreads();
    for (int i = tid; i < NTREES * NL; i += blockDim.x) {
        int t = i / NL, l = i % NL;
        const float* lg = params + t * PER_TREE + NI * DIM + NI + l * NC;
        float m = -1e30f;
        #pragma unroll
        for (int c = 0; c < NC; c++) m = fmaxf(m, lg[c]);
        float e[NC]; float s = 0.f;
        #pragma unroll
        for (int c = 0; c < NC; c++) { e[c] = __expf(lg[c] - m); s += e[c]; }
        float scale = tw[t] * __fdividef(1.0f, s);
        #pragma unroll
        for (int c = 0; c < NC; c++) g_lcp[i * NC + c] = e[c] * scale;
    }
}

// ---------------------------------------------------------------------------
// Main kernel: 256 threads; warp-half d-split; 1 owned row per thread.
// ---------------------------------------------------------------------------
__global__ __launch_bounds__(THREADS, 1)
void tree_main_kernel(const float* __restrict__ x,
                      const float* __restrict__ params,
                      float* __restrict__ out) {
    extern __shared__ float smem[];
    float* ws = smem;
    float* bs = smem + BS_OFF;
    float* zb = smem + ZB_OFF;
    float* xs = smem + XS_OFF;

    int tid = threadIdx.x;
    int h   = tid >> 7;          // d-half this thread computes (warp-uniform)
    int rb  = tid & 127;         // base row
    int orow = tid ^ 128;        // the row whose partial we ship to our partner

    // Stage weights/biases.
    for (int i = tid; i < WS_FLOATS; i += THREADS) {
        int t = i / (NI * DIM); int r = i - t * (NI * DIM);
        ws[i] = params[t * PER_TREE + r];
    }
    if (tid < NTREES * NI) {
        int t = tid / NI; int n = tid - t * NI;
        bs[tid] = params[t * PER_TREE + NI * DIM + n];
    }

    // Stage x tile: coalesced float4 global loads -> padded smem rows.
    const float4* xg = (const float4*)(x + (long)blockIdx.x * ROWS_PER_BLOCK * DIM);
    #pragma unroll
    for (int k = 0; k < (ROWS_PER_BLOCK * DIM / 4) / THREADS; k++) {
        int idx = k * THREADS + tid;
        int row = idx >> 5, c4 = idx & 31;
        ((float4*)(xs + row * XS_STRIDE))[c4] = xg[idx];
    }
    __syncthreads();

    // Register-load this thread's TWO half-rows: rows rb and rb+128,
    // columns [h*64, h*64+64). 16 LDS.128 each, conflict-free (stride 132).
    u64 xrA[HALF / 2], xrB[HALF / 2];
    {
        const ulonglong2* pa = (const ulonglong2*)(xs + rb * XS_STRIDE + h * HALF);
        const ulonglong2* pb = (const ulonglong2*)(xs + (rb + 128) * XS_STRIDE + h * HALF);
        #pragma unroll
        for (int j = 0; j < HALF / 4; j++) {
            ulonglong2 va = pa[j]; xrA[2*j] = va.x; xrA[2*j+1] = va.y;
            ulonglong2 vb = pb[j]; xrB[2*j] = vb.x; xrB[2*j+1] = vb.y;
        }
    }

    u64 outacc[5];
    #pragma unroll
    for (int c = 0; c < 5; c++) outacc[c] = 0ull;

    #pragma unroll 1
    for (int t = 0; t < NTREES; t++) {
        const float* wbase = ws + t * NI * DIM + h * HALF;
        u64 aA[NI], aB[NI];
        #pragma unroll
        for (int n = 0; n < NI; n++) { aA[n] = 0ull; aB[n] = 0ull; }

        // Half-GEMV: weight loads warp-uniform broadcast LDS.128 (112/tree/warp).
        #pragma unroll
        for (int d4 = 0; d4 < HALF / 4; d4++) {
            #pragma unroll
            for (int n = 0; n < NI; n++) {
                ulonglong2 wv = ((const ulonglong2*)(wbase + n * DIM))[d4];
                fma2(aA[n], xrA[2*d4],   wv.x);
                fma2(aA[n], xrA[2*d4+1], wv.y);
                fma2(aB[n], xrB[2*d4],   wv.x);
                fma2(aB[n], xrB[2*d4+1], wv.y);
            }
        }

        // Partial sums: own row = tid, other row = tid^128.
        float pown[NI], poth[NI];
        #pragma unroll
        for (int n = 0; n < NI; n++) {
            float2 fa = unpack2(aA[n]);
            float2 fb = unpack2(aB[n]);
            float sA = fa.x + fa.y;        // row rb
            float sB = fb.x + fb.y;        // row rb+128
            pown[n] = h ? sB : sA;
            poth[n] = h ? sA : sB;
        }

        // Exchange the other row's partial via padded smem (stride 9, 1wf).
        float* zw = zb + (t & 1) * ZB_STRIDE;
        #pragma unroll
        for (int n = 0; n < NI; n++) zw[orow * 9 + n] = poth[n];
        __syncthreads();

        // Full z for owned row -> sigmoid.
        float p[NI];
        #pragma unroll
        for (int n = 0; n < NI; n++) {
            float z = pown[n] + zw[tid * 9 + n] + bs[t * NI + n];
            p[n] = fast_sigmoid(z);
        }

        // Leaf path products.
        float lp[NL];
        {
            float c1 = 1.f - p[0], c2 = p[0];
            float c3 = c1 * (1.f - p[1]), c4v = c1 * p[1];
            float c5 = c2 * (1.f - p[2]), c6 = c2 * p[2];
            lp[0] = c3 * (1.f - p[3]);  lp[1] = c3 * p[3];
            lp[2] = c4v * (1.f - p[4]); lp[3] = c4v * p[4];
            lp[4] = c5 * (1.f - p[5]);  lp[5] = c5 * p[5];
            lp[6] = c6 * (1.f - p[6]);  lp[7] = c6 * p[6];
        }

        // Class mix; lcp (pre-scaled by tree weight) from constant memory.
        const u64* lt = (const u64*)(c_lcp + t * NL * NC);
        #pragma unroll
        for (int l = 0; l < NL; l++) {
            u64 s = splat2(lp[l]);
            #pragma unroll
            for (int c = 0; c < 5; c++) fma2(outacc[c], s, lt[l * 5 + c]);
        }
    }

    // Write owned row's 10 floats as 5 float2 stores.
    float2* og = (float2*)(out + ((long)blockIdx.x * ROWS_PER_BLOCK + tid) * NC);
    #pragma unroll
    for (int c = 0; c < 5; c++) og[c] = unpack2(outacc[c]);
}

// ---------------------------------------------------------------------------
extern "C" void kernel_launch(void* const* d_in, const int* in_sizes, int n_in,
                              void* d_out, int out_size) {
    const float* x      = (const float*)d_in[0];
    const float* params = (const float*)d_in[1];
    float* out          = (float*)d_out;
    int batch = in_sizes[0] / DIM;

    cudaFuncSetAttribute(tree_main_kernel,
                         cudaFuncAttributeMaxDynamicSharedMemorySize, SMEM_BYTES);

    prep_kernel<<<1, 128>>>(params);

    // Move the prepped leaf-class table into __constant__ (D2D memcpy node,
    // graph-capturable, ordered after prep_kernel on the same stream).
    void* lcp_dev = nullptr;
    cudaGetSymbolAddress(&lcp_dev, g_lcp);
    cudaMemcpyToSymbolAsync(c_lcp, lcp_dev, NTREES * NL * NC * sizeof(float),
                            0, cudaMemcpyDeviceToDevice, 0);

    tree_main_kernel<<<batch / ROWS_PER_BLOCK, THREADS, SMEM_BYTES>>>(x, params, out);
}

// round 15
// speedup vs baseline: 1.9078x; 1.5636x over previous
#include <cuda_runtime.h>
#include <cstdint>

// Soft decision tree ensemble via portable warp-level MMA (mma.sync bf16).
//   N_TREES=15, DEPTH=3 (7 internal, 8 leaves), INPUT_DIM=128, N_CLASSES=10, batch=262144
//
// R12: tcgen05 is not compilable here (harness emits PTX for base sm_103, no 'a'
// feature set). Use mma.sync.aligned.m16n8k16.row.col.f32.bf16.bf16.f32 — baseline
// PTX since sm_80, runs on the Blackwell tensor pipe.
//
//   z = xh.wh + xh.wl + xl.wh   (3-term bf16 split, fp32 accum; lo.lo ~2^-18 dropped)
//
// Per CTA (256 rows, 8 warps; warp w owns rows [32w, 32w+32)):
//   1. stage x -> smem bf16 hi/lo tiles [256][136] (pad stride: 68 words = 4 mod 32
//      -> conflict-free fragment LDS.32); stage w -> [112][136] hi/lo (105 real rows).
//   2. 3 passes x 8 k16-steps x (2 m16-tiles x 14 n8-tiles) mma.sync, 112 f32 acc/thread.
//   3. z -> smem [256][141] (stride 141 = 13 mod 32: g*S+2*tg injective mod 32 ->
//      conflict-free stores and per-row reads), reusing the dead A/B tile space.
//   4. per-thread epilogue: bias+sigmoid -> leaf path products -> class mix with
//      tree-weight-prescaled leaf-class probs from __constant__.

#define NTREES 15
#define NI 7
#define NL 8
#define NC 10
#define DIM 128
#define PER_TREE (NI*DIM + NI + NL*NC)   // 983
#define NOUT (NTREES*NI)                 // 105
#define NB 112                           // padded (14 n8-tiles)
#define ROWS 256
#define THREADS 256

// smem layout (bytes from dynamic base; base is 1024-aligned)
#define A_OFF   1024
#define A_STRIDE_B 272                   // 136 bf16 per row
#define A_TILE  (ROWS*A_STRIDE_B)        // 69632
#define B_OFF   (A_OFF + 2*A_TILE)       // 140288
#define B_STRIDE_B 272
#define B_TILE  (NB*B_STRIDE_B)          // 30464
#define SMEM_BYTES (B_OFF + 2*B_TILE)    // 201216
#define Z_STRIDE 141                     // floats; 141 mod 32 = 13 (conflict-free)

#define G_META (NTREES*NL*NC + NB)       // 1200 lcp + 112 bias

typedef unsigned long long u64;
typedef unsigned int u32;

__device__    float g_meta[G_META];
__constant__  float c_meta[G_META];

// ---------------- helpers ----------------
__device__ __forceinline__ void fma2(u64 &d, u64 a, u64 b) {
    asm("fma.rn.f32x2 %0, %1, %2, %0;" : "+l"(d) : "l"(a), "l"(b));
}
__device__ __forceinline__ u64 splat2(float f) {
    u64 r; asm("mov.b64 %0, {%1, %1};" : "=l"(r) : "f"(f)); return r;
}
__device__ __forceinline__ float2 unpack2(u64 v) {
    float2 f; asm("mov.b64 {%0, %1}, %2;" : "=f"(f.x), "=f"(f.y) : "l"(v)); return f;
}
__device__ __forceinline__ float fast_sigmoid(float z) {
    return __fdividef(1.0f, 1.0f + __expf(-z));
}
__device__ __forceinline__ u32 pack_bf16(float hi, float lo) {
    u32 r; asm("cvt.rn.bf16x2.f32 %0, %1, %2;" : "=r"(r) : "f"(hi), "f"(lo));
    return r;
}
__device__ __forceinline__ u32 smem_u32(const void* p) {
    u32 a; asm("{ .reg .u64 t; cvta.to.shared.u64 t, %1; cvt.u32.u64 %0, t; }"
               : "=r"(a) : "l"(p));
    return a;
}
__device__ __forceinline__ u32 lds32(u32 addr) {
    u32 v; asm volatile("ld.shared.b32 %0, [%1];" : "=r"(v) : "r"(addr));
    return v;
}
__device__ __forceinline__ void sts32(u32 addr, u32 v) {
    asm volatile("st.shared.b32 [%0], %1;" :: "r"(addr), "r"(v) : "memory");
}
__device__ __forceinline__ void mma16816(float* c, u32 a0, u32 a1, u32 a2, u32 a3,
                                         u32 b0, u32 b1) {
    asm volatile(
        "mma.sync.aligned.m16n8k16.row.col.f32.bf16.bf16.f32 "
        "{%0,%1,%2,%3}, {%4,%5,%6,%7}, {%8,%9}, {%0,%1,%2,%3};"
        : "+f"(c[0]), "+f"(c[1]), "+f"(c[2]), "+f"(c[3])
        : "r"(a0), "r"(a1), "r"(a2), "r"(a3), "r"(b0), "r"(b1));
}

// ---------------------------------------------------------------------------
// Prep: tree-weight softmax + leaf-logit softmax (prescaled) + biases.
// ---------------------------------------------------------------------------
__global__ void prep_kernel(const float* __restrict__ params) {
    __shared__ float tw[NTREES];
    int tid = threadIdx.x;
    if (tid == 0) {
        const float* twl = params + NTREES * PER_TREE;
        float m = -1e30f;
        for (int t = 0; t < NTREES; t++) m = fmaxf(m, twl[t]);
        float e[NTREES]; float s = 0.f;
        for (int t = 0; t < NTREES; t++) { e[t] = __expf(twl[t] - m); s += e[t]; }
        float inv = __fdividef(1.0f, s);
        for (int t = 0; t < NTREES; t++) tw[t] = e[t] * inv;
    }
    __syncthreads();
    for (int i = tid; i < NTREES * NL; i += blockDim.x) {
        int t = i / NL, l = i % NL;
        const float* lg = params + t * PER_TREE + NI * DIM + NI + l * NC;
        float m = -1e30f;
        #pragma unroll
        for (int c = 0; c < NC; c++) m = fmaxf(m, lg[c]);
        float e[NC]; float s = 0.f;
        #pragma unroll
        for (int c = 0; c < NC; c++) { e[c] = __expf(lg[c] - m); s += e[c]; }
        float scale = tw[t] * __fdividef(1.0f, s);
        #pragma unroll
        for (int c = 0; c < NC; c++) g_meta[i * NC + c] = e[c] * scale;
    }
    for (int i = tid; i < NB; i += blockDim.x) {
        float b = 0.f;
        if (i < NOUT) {
            int t = i / NI, n = i - t * NI;
            b = params[t * PER_TREE + NI * DIM + n];
        }
        g_meta[NTREES * NL * NC + i] = b;
    }
}

// ---------------------------------------------------------------------------
// Main kernel
// ---------------------------------------------------------------------------
__global__ __launch_bounds__(THREADS, 1)
void tree_mma_kernel(const float* __restrict__ x,
                     const float* __restrict__ params,
                     float* __restrict__ out) {
    extern __shared__ __align__(1024) char smem[];
    u32 sb = smem_u32(smem);
    float* zsf = (float*)(smem + A_OFF);     // z exchange reuses A/B space post-MMA
    int tid = threadIdx.x;
    int wid  = tid >> 5;
    int lane = tid & 31;
    int g  = lane >> 2;                      // group row (0..7)
    int tg = lane & 3;                       // thread-in-group (0..3)

    // ---- Stage A: x -> bf16 hi/lo [256][136] ------------------------------
    const float2* xg = (const float2*)(x + (size_t)blockIdx.x * ROWS * DIM);
    #pragma unroll 8
    for (int it = 0; it < (ROWS * DIM / 2) / THREADS; it++) {
        int p = it * THREADS + tid;
        float2 v = xg[p];
        int row = p >> 6;
        int kp  = p & 63;                    // bf16-pair index within row
        u32 hi = pack_bf16(v.y, v.x);
        float h0 = __uint_as_float(hi << 16);
        float h1 = __uint_as_float(hi & 0xFFFF0000u);
        u32 lo = pack_bf16(v.y - h1, v.x - h0);
        u32 addr = sb + A_OFF + row * A_STRIDE_B + kp * 4;
        sts32(addr, hi);
        sts32(addr + A_TILE, lo);
    }

    // ---- Stage B: w -> bf16 hi/lo [112][136] (rows >=105 zeroed) ----------
    #pragma unroll 4
    for (int it = 0; it < (NB * DIM / 2) / THREADS; it++) {
        int i  = it * THREADS + tid;
        int n  = i >> 6;
        int kp = i & 63;
        float w0 = 0.f, w1 = 0.f;
        if (n < NOUT) {
            int t = n / NI, node = n - t * NI;
            const float* wp = params + t * PER_TREE + node * DIM + kp * 2;
            w0 = wp[0]; w1 = wp[1];
        }
        u32 hi = pack_bf16(w1, w0);
        float h0 = __uint_as_float(hi << 16);
        float h1 = __uint_as_float(hi & 0xFFFF0000u);
        u32 lo = pack_bf16(w1 - h1, w0 - h0);
        u32 addr = sb + B_OFF + n * B_STRIDE_B + kp * 4;
        sts32(addr, hi);
        sts32(addr + B_TILE, lo);
    }
    __syncthreads();

    // ---- MMA: 3 passes (AhBh, AhBl, AlBh), warp stripe = 32 rows ----------
    int stripe = wid * 32;
    float acc[2][14][4];
    #pragma unroll
    for (int m = 0; m < 2; m++)
        #pragma unroll
        for (int nt = 0; nt < 14; nt++)
            #pragma unroll
            for (int r = 0; r < 4; r++) acc[m][nt][r] = 0.f;

    #pragma unroll 1
    for (int pass = 0; pass < 3; pass++) {
        u32 Ab = sb + A_OFF + (pass == 2 ? A_TILE : 0);
        u32 Bb = sb + B_OFF + (pass == 1 ? B_TILE : 0);
        u32 Abase = Ab + (stripe + g) * A_STRIDE_B + tg * 4;
        u32 Bbase = Bb + g * B_STRIDE_B + tg * 4;
        #pragma unroll
        for (int ks = 0; ks < 8; ks++) {
            u32 ka = ks * 32;                          // 8 words per k16 step
            // A fragments, m-tile 0 (rows stripe+g, +8) and 1 (+16, +24)
            u32 aA = Abase + ka;
            u32 a00 = lds32(aA);
            u32 a01 = lds32(aA + 8 * A_STRIDE_B);
            u32 a02 = lds32(aA + 16);
            u32 a03 = lds32(aA + 8 * A_STRIDE_B + 16);
            u32 aB = aA + 16 * A_STRIDE_B;
            u32 a10 = lds32(aB);
            u32 a11 = lds32(aB + 8 * A_STRIDE_B);
            u32 a12 = lds32(aB + 16);
            u32 a13 = lds32(aB + 8 * A_STRIDE_B + 16);
            #pragma unroll
            for (int nt = 0; nt < 14; nt++) {
                u32 bA = Bbase + nt * 8 * B_STRIDE_B + ka;
                u32 b0 = lds32(bA);
                u32 b1 = lds32(bA + 16);
                mma16816(acc[0][nt], a00, a01, a02, a03, b0, b1);
                mma16816(acc[1][nt], a10, a11, a12, a13, b0, b1);
            }
        }
    }

    // ---- z exchange through smem (A/B tiles are dead now) -----------------
    __syncthreads();
    #pragma unroll
    for (int m = 0; m < 2; m++) {
        int r0 = stripe + m * 16 + g;
        #pragma unroll
        for (int nt = 0; nt < 14; nt++) {
            int col = nt * 8 + tg * 2;
            zsf[r0 * Z_STRIDE + col]           = acc[m][nt][0];
            zsf[r0 * Z_STRIDE + col + 1]       = acc[m][nt][1];
            zsf[(r0 + 8) * Z_STRIDE + col]     = acc[m][nt][2];
            zsf[(r0 + 8) * Z_STRIDE + col + 1] = acc[m][nt][3];
        }
    }
    __syncthreads();

    // ---- Epilogue: row = tid ---------------------------------------------
    const float* zr   = zsf + tid * Z_STRIDE;
    const float* bias = c_meta + NTREES * NL * NC;
    u64 outacc[5];
    #pragma unroll
    for (int c = 0; c < 5; c++) outacc[c] = 0ull;

    #pragma unroll
    for (int t = 0; t < NTREES; t++) {
        float p[NI];
        #pragma unroll
        for (int n = 0; n < NI; n++) {
            float z = zr[t * NI + n] + bias[t * NI + n];
            p[n] = fast_sigmoid(z);
        }
        float lp[NL];
        {
            float c1 = 1.f - p[0], c2 = p[0];
            float c3 = c1 * (1.f - p[1]), c4v = c1 * p[1];
            float c5 = c2 * (1.f - p[2]), c6 = c2 * p[2];
            lp[0] = c3 * (1.f - p[3]);  lp[1] = c3 * p[3];
            lp[2] = c4v * (1.f - p[4]); lp[3] = c4v * p[4];
            lp[4] = c5 * (1.f - p[5]);  lp[5] = c5 * p[5];
            lp[6] = c6 * (1.f - p[6]);  lp[7] = c6 * p[6];
        }
        const u64* lt = (const u64*)(c_meta + t * NL * NC);
        #pragma unroll
        for (int l = 0; l < NL; l++) {
            u64 s = splat2(lp[l]);
            #pragma unroll
            for (int c = 0; c < 5; c++) fma2(outacc[c], s, lt[l * 5 + c]);
        }
    }

    float2* og = (float2*)(out + ((size_t)blockIdx.x * ROWS + tid) * NC);
    #pragma unroll
    for (int c = 0; c < 5; c++) og[c] = unpack2(outacc[c]);
}

// ---------------------------------------------------------------------------
extern "C" void kernel_launch(void* const* d_in, const int* in_sizes, int n_in,
                              void* d_out, int out_size) {
    const float* x      = (const float*)d_in[0];
    const float* params = (const float*)d_in[1];
    float* out          = (float*)d_out;
    int batch = in_sizes[0] / DIM;

    cudaFuncSetAttribute(tree_mma_kernel,
                         cudaFuncAttributeMaxDynamicSharedMemorySize, SMEM_BYTES);

    prep_kernel<<<1, 128>>>(params);

    void* meta_dev = nullptr;
    cudaGetSymbolAddress(&meta_dev, g_meta);
    cudaMemcpyToSymbolAsync(c_meta, meta_dev, G_META * sizeof(float),
                            0, cudaMemcpyDeviceToDevice, 0);

    tree_mma_kernel<<<batch / ROWS, THREADS, SMEM_BYTES>>>(x, params, out);
}

// round 17
// speedup vs baseline: 2.0901x; 1.0956x over previous
#include <cuda_runtime.h>
#include <cstdint>

// Soft decision tree ensemble via portable warp-level MMA (mma.sync bf16).
//   N_TREES=15, DEPTH=3 (7 internal, 8 leaves), INPUT_DIM=128, N_CLASSES=10, batch=262144
//
// R15: R12 tensor-core pipeline, rebalanced for latency hiding:
//   - 512 threads (16 warps = 4/SMSP, occ 12.5%->25%): warp (mg,ng) computes
//     m-tiles {2mg,2mg+1} x n-tiles {7ng..7ng+6}; per-warp issue ~halves.
//   - z = xh.wh + xh.wl + xl.wh (3-term bf16 split, fp32 accum; lo.lo dropped)
//   - epilogue split per row across thread pairs (trees 0-7 / 8-14), partials
//     combined via stride-13 smem buffer in the dead B-tile region.

#define NTREES 15
#define NI 7
#define NL 8
#define NC 10
#define DIM 128
#define PER_TREE (NI*DIM + NI + NL*NC)   // 983
#define NOUT (NTREES*NI)                 // 105
#define NB 112                           // padded (14 n8-tiles)
#define ROWS 256
#define THREADS 512

// smem layout (bytes from dynamic base; base is 1024-aligned)
#define A_OFF   1024
#define A_STRIDE_B 272                   // 136 bf16 per row
#define A_TILE  (ROWS*A_STRIDE_B)        // 69632
#define B_OFF   (A_OFF + 2*A_TILE)       // 140288
#define B_STRIDE_B 272
#define B_TILE  (NB*B_STRIDE_B)          // 30464
#define SMEM_BYTES (B_OFF + 2*B_TILE)    // 201216
#define Z_STRIDE 141                     // floats; 141 mod 32 = 13 (conflict-free)
#define P_OFF   150528                   // partial-sum buffer (dead B region)
#define P_STRIDE 13                      // floats, gcd(13,32)=1 -> conflict-free

#define G_META (NTREES*NL*NC + NB)       // 1200 lcp + 112 bias

typedef unsigned long long u64;
typedef unsigned int u32;

__device__    float g_meta[G_META];
__constant__  float c_meta[G_META];

// ---------------- helpers ----------------
__device__ __forceinline__ void fma2(u64 &d, u64 a, u64 b) {
    asm("fma.rn.f32x2 %0, %1, %2, %0;" : "+l"(d) : "l"(a), "l"(b));
}
__device__ __forceinline__ u64 splat2(float f) {
    u64 r; asm("mov.b64 %0, {%1, %1};" : "=l"(r) : "f"(f)); return r;
}
__device__ __forceinline__ float2 unpack2(u64 v) {
    float2 f; asm("mov.b64 {%0, %1}, %2;" : "=f"(f.x), "=f"(f.y) : "l"(v)); return f;
}
__device__ __forceinline__ float fast_sigmoid(float z) {
    return __fdividef(1.0f, 1.0f + __expf(-z));
}
__device__ __forceinline__ u32 pack_bf16(float hi, float lo) {
    u32 r; asm("cvt.rn.bf16x2.f32 %0, %1, %2;" : "=r"(r) : "f"(hi), "f"(lo));
    return r;
}
__device__ __forceinline__ u32 smem_u32(const void* p) {
    u32 a; asm("{ .reg .u64 t; cvta.to.shared.u64 t, %1; cvt.u32.u64 %0, t; }"
               : "=r"(a) : "l"(p));
    return a;
}
__device__ __forceinline__ u32 lds32(u32 addr) {
    u32 v; asm volatile("ld.shared.b32 %0, [%1];" : "=r"(v) : "r"(addr));
    return v;
}
__device__ __forceinline__ void sts32(u32 addr, u32 v) {
    asm volatile("st.shared.b32 [%0], %1;" :: "r"(addr), "r"(v) : "memory");
}
__device__ __forceinline__ void mma16816(float* c, u32 a0, u32 a1, u32 a2, u32 a3,
                                         u32 b0, u32 b1) {
    asm volatile(
        "mma.sync.aligned.m16n8k16.row.col.f32.bf16.bf16.f32 "
        "{%0,%1,%2,%3}, {%4,%5,%6,%7}, {%8,%9}, {%0,%1,%2,%3};"
        : "+f"(c[0]), "+f"(c[1]), "+f"(c[2]), "+f"(c[3])
        : "r"(a0), "r"(a1), "r"(a2), "r"(a3), "r"(b0), "r"(b1));
}

// ---------------------------------------------------------------------------
// Prep: tree-weight softmax + leaf-logit softmax (prescaled) + biases.
// ---------------------------------------------------------------------------
__global__ void prep_kernel(const float* __restrict__ params) {
    __shared__ float tw[NTREES];
    int tid = threadIdx.x;
    if (tid == 0) {
        const float* twl = params + NTREES * PER_TREE;
        float m = -1e30f;
        for (int t = 0; t < NTREES; t++) m = fmaxf(m, twl[t]);
        float e[NTREES]; float s = 0.f;
        for (int t = 0; t < NTREES; t++) { e[t] = __expf(twl[t] - m); s += e[t]; }
        float inv = __fdividef(1.0f, s);
        for (int t = 0; t < NTREES; t++) tw[t] = e[t] * inv;
    }
    __syncthreads();
    for (int i = tid; i < NTREES * NL; i += blockDim.x) {
        int t = i / NL, l = i % NL;
        const float* lg = params + t * PER_TREE + NI * DIM + NI + l * NC;
        float m = -1e30f;
        #pragma unroll
        for (int c = 0; c < NC; c++) m = fmaxf(m, lg[c]);
        float e[NC]; float s = 0.f;
        #pragma unroll
        for (int c = 0; c < NC; c++) { e[c] = __expf(lg[c] - m); s += e[c]; }
        float scale = tw[t] * __fdividef(1.0f, s);
        #pragma unroll
        for (int c = 0; c < NC; c++) g_meta[i * NC + c] = e[c] * scale;
    }
    for (int i = tid; i < NB; i += blockDim.x) {
        float b = 0.f;
        if (i < NOUT) {
            int t = i / NI, n = i - t * NI;
            b = params[t * PER_TREE + NI * DIM + n];
        }
        g_meta[NTREES * NL * NC + i] = b;
    }
}

// ---------------------------------------------------------------------------
// Main kernel
// ---------------------------------------------------------------------------
__global__ __launch_bounds__(THREADS, 1)
void tree_mma_kernel(const float* __restrict__ x,
                     const float* __restrict__ params,
                     float* __restrict__ out) {
    extern __shared__ __align__(1024) char smem[];
    u32 sb = smem_u32(smem);
    float* zsf  = (float*)(smem + A_OFF);    // z exchange reuses A tiles post-MMA
    float* pbuf = (float*)(smem + P_OFF);    // epilogue partials (dead B region)
    int tid = threadIdx.x;
    int wid  = tid >> 5;
    int lane = tid & 31;
    int g  = lane >> 2;                      // group row (0..7)
    int tg = lane & 3;                       // thread-in-group (0..3)

    // ---- Stage A: x -> bf16 hi/lo [256][136] ------------------------------
    const float2* xg = (const float2*)(x + (size_t)blockIdx.x * ROWS * DIM);
    #pragma unroll 8
    for (int it = 0; it < (ROWS * DIM / 2) / THREADS; it++) {
        int p = it * THREADS + tid;
        float2 v = xg[p];
        int row = p >> 6;
        int kp  = p & 63;
        u32 hi = pack_bf16(v.y, v.x);
        float h0 = __uint_as_float(hi << 16);
        float h1 = __uint_as_float(hi & 0xFFFF0000u);
        u32 lo = pack_bf16(v.y - h1, v.x - h0);
        u32 addr = sb + A_OFF + row * A_STRIDE_B + kp * 4;
        sts32(addr, hi);
        sts32(addr + A_TILE, lo);
    }

    // ---- Stage B: w -> bf16 hi/lo [112][136] (rows >=105 zeroed) ----------
    #pragma unroll 4
    for (int it = 0; it < (NB * DIM / 2) / THREADS; it++) {
        int i  = it * THREADS + tid;
        int n  = i >> 6;
        int kp = i & 63;
        float w0 = 0.f, w1 = 0.f;
        if (n < NOUT) {
            int t = n / NI, node = n - t * NI;
            const float* wp = params + t * PER_TREE + node * DIM + kp * 2;
            w0 = wp[0]; w1 = wp[1];
        }
        u32 hi = pack_bf16(w1, w0);
        float h0 = __uint_as_float(hi << 16);
        float h1 = __uint_as_float(hi & 0xFFFF0000u);
        u32 lo = pack_bf16(w1 - h1, w0 - h0);
        u32 addr = sb + B_OFF + n * B_STRIDE_B + kp * 4;
        sts32(addr, hi);
        sts32(addr + B_TILE, lo);
    }
    __syncthreads();

    // ---- MMA: 3 passes; warp (mg,ng) does 2 m-tiles x 7 n-tiles -----------
    int mg = wid >> 1;                       // m-group 0..7 -> rows [32mg, 32mg+32)
    int ng = wid & 1;                        // n-group 0..1 -> n-tiles [7ng, 7ng+7)
    int stripe = mg * 32;
    float acc[2][7][4];
    #pragma unroll
    for (int m = 0; m < 2; m++)
        #pragma unroll
        for (int nt = 0; nt < 7; nt++)
            #pragma unroll
            for (int r = 0; r < 4; r++) acc[m][nt][r] = 0.f;

    #pragma unroll 1
    for (int pass = 0; pass < 3; pass++) {
        u32 Ab = sb + A_OFF + (pass == 2 ? A_TILE : 0);
        u32 Bb = sb + B_OFF + (pass == 1 ? B_TILE : 0);
        u32 Abase = Ab + (stripe + g) * A_STRIDE_B + tg * 4;
        u32 Bbase = Bb + (ng * 56 + g) * B_STRIDE_B + tg * 4;
        #pragma unroll
        for (int ks = 0; ks < 8; ks++) {
            u32 ka = ks * 32;
            u32 aA = Abase + ka;
            u32 a00 = lds32(aA);
            u32 a01 = lds32(aA + 8 * A_STRIDE_B);
            u32 a02 = lds32(aA + 16);
            u32 a03 = lds32(aA + 8 * A_STRIDE_B + 16);
            u32 aB = aA + 16 * A_STRIDE_B;
            u32 a10 = lds32(aB);
            u32 a11 = lds32(aB + 8 * A_STRIDE_B);
            u32 a12 = lds32(aB + 16);
            u32 a13 = lds32(aB + 8 * A_STRIDE_B + 16);
            #pragma unroll
            for (int nt = 0; nt < 7; nt++) {
                u32 bA = Bbase + nt * 8 * B_STRIDE_B + ka;
                u32 b0 = lds32(bA);
                u32 b1 = lds32(bA + 16);
                mma16816(acc[0][nt], a00, a01, a02, a03, b0, b1);
                mma16816(acc[1][nt], a10, a11, a12, a13, b0, b1);
            }
        }
    }

    // ---- z exchange through smem (A/B hi tiles are dead now) --------------
    __syncthreads();
    #pragma unroll
    for (int m = 0; m < 2; m++) {
        int r0 = stripe + m * 16 + g;
        #pragma unroll
        for (int nt = 0; nt < 7; nt++) {
            int col = ng * 56 + nt * 8 + tg * 2;
            zsf[r0 * Z_STRIDE + col]           = acc[m][nt][0];
            zsf[r0 * Z_STRIDE + col + 1]       = acc[m][nt][1];
            zsf[(r0 + 8) * Z_STRIDE + col]     = acc[m][nt][2];
            zsf[(r0 + 8) * Z_STRIDE + col + 1] = acc[m][nt][3];
        }
    }
    __syncthreads();

    // ---- Epilogue: row = tid&255; half 0 trees 0-7, half 1 trees 8-14 -----
    int row = tid & 255;
    int hf  = tid >> 8;
    const float* zr   = zsf + row * Z_STRIDE;
    const float* bias = c_meta + NTREES * NL * NC;
    u64 outacc[5];
    #pragma unroll
    for (int c = 0; c < 5; c++) outacc[c] = 0ull;

    if (hf == 0) {
        #pragma unroll
        for (int t = 0; t < 8; t++) {
            float p[NI];
            #pragma unroll
            for (int n = 0; n < NI; n++)
                p[n] = fast_sigmoid(zr[t * NI + n] + bias[t * NI + n]);
            float lp[NL];
            float c1 = 1.f - p[0], c2 = p[0];
            float c3 = c1 * (1.f - p[1]), c4v = c1 * p[1];
            float c5 = c2 * (1.f - p[2]), c6 = c2 * p[2];
            lp[0] = c3 * (1.f - p[3]);  lp[1] = c3 * p[3];
            lp[2] = c4v * (1.f - p[4]); lp[3] = c4v * p[4];
            lp[4] = c5 * (1.f - p[5]);  lp[5] = c5 * p[5];
            lp[6] = c6 * (1.f - p[6]);  lp[7] = c6 * p[6];
            const u64* lt = (const u64*)(c_meta + t * NL * NC);
            #pragma unroll
            for (int l = 0; l < NL; l++) {
                u64 s = splat2(lp[l]);
                #pragma unroll
                for (int c = 0; c < 5; c++) fma2(outacc[c], s, lt[l * 5 + c]);
            }
        }
    } else {
        #pragma unroll
        for (int t = 8; t < 15; t++) {
            float p[NI];
            #pragma unroll
            for (int n = 0; n < NI; n++)
                p[n] = fast_sigmoid(zr[t * NI + n] + bias[t * NI + n]);
            float lp[NL];
            float c1 = 1.f - p[0], c2 = p[0];
            float c3 = c1 * (1.f - p[1]), c4v = c1 * p[1];
            float c5 = c2 * (1.f - p[2]), c6 = c2 * p[2];
            lp[0] = c3 * (1.f - p[3]);  lp[1] = c3 * p[3];
            lp[2] = c4v * (1.f - p[4]); lp[3] = c4v * p[4];
            lp[4] = c5 * (1.f - p[5]);  lp[5] = c5 * p[5];
            lp[6] = c6 * (1.f - p[6]);  lp[7] = c6 * p[6];
            const u64* lt = (const u64*)(c_meta + t * NL * NC);
            #pragma unroll
            for (int l = 0; l < NL; l++) {
                u64 s = splat2(lp[l]);
                #pragma unroll
                for (int c = 0; c < 5; c++) fma2(outacc[c], s, lt[l * 5 + c]);
            }
        }
        // publish partials
        #pragma unroll
        for (int c = 0; c < 5; c++) {
            float2 v = unpack2(outacc[c]);
            pbuf[row * P_STRIDE + 2 * c]     = v.x;
            pbuf[row * P_STRIDE + 2 * c + 1] = v.y;
        }
    }
    __syncthreads();

    if (hf == 0) {
        float2* og = (float2*)(out + ((size_t)blockIdx.x * ROWS + row) * NC);
        #pragma unroll
        for (int c = 0; c < 5; c++) {
            float2 v = unpack2(outacc[c]);
            v.x += pbuf[row * P_STRIDE + 2 * c];
            v.y += pbuf[row * P_STRIDE + 2 * c + 1];
            og[c] = v;
        }
    }
}

// ---------------------------------------------------------------------------
extern "C" void kernel_launch(void* const* d_in, const int* in_sizes, int n_in,
                              void* d_out, int out_size) {
    const float* x      = (const float*)d_in[0];
    const float* params = (const float*)d_in[1];
    float* out          = (float*)d_out;
    int batch = in_sizes[0] / DIM;

    cudaFuncSetAttribute(tree_mma_kernel,
                         cudaFuncAttributeMaxDynamicSharedMemorySize, SMEM_BYTES);

    prep_kernel<<<1, 128>>>(params);

    void* meta_dev = nullptr;
    cudaGetSymbolAddress(&meta_dev, g_meta);
    cudaMemcpyToSymbolAsync(c_meta, meta_dev, G_META * sizeof(float),
                            0, cudaMemcpyDeviceToDevice, 0);

    tree_mma_kernel<<<batch / ROWS, THREADS, SMEM_BYTES>>>(x, params, out);
}